// round 10
// baseline (speedup 1.0000x reference)
#include <cuda_runtime.h>
#include <cuda_fp16.h>
#include <cstdint>

#define B_ 256
#define N_ 64
#define T_ 4096
#define H_ 16
#define SLICES_ 16          // CTAs per batch, each owns 256 t

typedef unsigned int uint32;

__device__ float2 g_part[B_ * SLICES_ * N_];   // per (batch,slice,row): (sum, sumsq)
__device__ unsigned int g_cnt[B_];

// ---------- helpers ----------
static __device__ __forceinline__ uint32 smem_u32(const void* p) {
    uint32 a;
    asm("{ .reg .u64 t; cvta.to.shared.u64 t, %1; cvt.u32.u64 %0, t; }" : "=r"(a) : "l"(p));
    return a;
}
static __device__ __forceinline__ uint32 pack_f16x2(float f0, float f1) {
    uint32 r;
    asm("cvt.rn.f16x2.f32 %0, %1, %2;" : "=r"(r) : "f"(f1), "f"(f0));
    return r;
}
static __device__ __forceinline__ float2 h2f2(uint32 u) {
    __half2 h = *(__half2*)&u;
    return __half22float2(h);
}
static __device__ __forceinline__ void split_pair_f16(float f0, float f1, uint32& h, uint32& l) {
    h = pack_f16x2(f0, f1);
    float2 b = h2f2(h);
    l = pack_f16x2(f0 - b.x, f1 - b.y);
}

#define MMA_F16(c, a0, a1, a2, a3, b0, b1) \
    asm volatile("mma.sync.aligned.m16n8k16.row.col.f32.f16.f16.f32 " \
        "{%0,%1,%2,%3}, {%4,%5,%6,%7}, {%8,%9}, {%0,%1,%2,%3};" \
        : "+f"((c)[0]), "+f"((c)[1]), "+f"((c)[2]), "+f"((c)[3]) \
        : "r"(a0), "r"(a1), "r"(a2), "r"(a3), "r"(b0), "r"(b1))

#define LDSM_X4_T(r0, r1, r2, r3, addr) \
    asm volatile("ldmatrix.sync.aligned.m8n8.x4.trans.shared.b16 {%0,%1,%2,%3}, [%4];" \
        : "=r"(r0), "=r"(r1), "=r"(r2), "=r"(r3) : "r"(addr))

// ---------- K0: reset per-batch arrival counters (each graph replay) ----------
__global__ void k_zero() { g_cnt[threadIdx.x] = 0u; }

// ---------- fused kernel ----------
// grid = (SLICES_, B_): CTA = (slice, batch). Contiguous launch order within a batch
// (x-major) + resident wave (~296 CTAs) >> 16 => spin-sync is deadlock-free.
#define SATT_STRIDE 68
__global__ void __launch_bounds__(256, 2) k_fused(const float* __restrict__ x,
                                                  const float* __restrict__ Wq,
                                                  const float* __restrict__ bq,
                                                  const float* __restrict__ Wk,
                                                  const float* __restrict__ bk,
                                                  float* __restrict__ attnw,
                                                  float* __restrict__ out) {
    extern __shared__ uint32 smem[];
    uint32* sXh = smem;                       // [64][128] f16x2 hi  (32KB)
    uint32* sXl = smem + 64 * 128;            // [64][128] f16x2 lo  (32KB)
    float* sAttn = (float*)(smem + 2 * 64 * 128);   // [64][SATT_STRIDE] (17.4KB)
    float* es = sAttn + 64 * SATT_STRIDE;           // [64]

    int slice = blockIdx.x;
    int b = blockIdx.y;
    int t_cta = slice * 256;
    int tid = threadIdx.x;
    int lane = tid & 31;
    int wid = tid >> 5;
    int it = wid & 3;
    int th = wid >> 2;
    int g = lane >> 2;
    int cq = lane & 3;

    const float* xb = x + (size_t)b * (N_ * T_);
    float* ob = out + (size_t)b * (N_ * T_);

    // ---- pass 1: stage x slice -> swizzled fp16 hi/lo smem, accumulate sum/sumsq ----
    {
        int j = tid >> 2, q = tid & 3;
        const float* xrow = xb + (size_t)j * T_ + t_cta;
        char* bh = (char*)(sXh + j * 128);
        char* bl = (char*)(sXl + j * 128);
        int sw = j & 7;
        float s = 0.f, ss = 0.f;
#pragma unroll
        for (int cc = 0; cc < 8; cc++) {
            int c = q + cc * 4;
            float4 a = *(const float4*)(xrow + c * 8);
            float4 d = *(const float4*)(xrow + c * 8 + 4);
            s  += (a.x + a.y) + (a.z + a.w) + (d.x + d.y) + (d.z + d.w);
            ss += (a.x * a.x + a.y * a.y) + (a.z * a.z + a.w * a.w)
                + (d.x * d.x + d.y * d.y) + (d.z * d.z + d.w * d.w);
            uint4 vh, vl;
            split_pair_f16(a.x, a.y, vh.x, vl.x);
            split_pair_f16(a.z, a.w, vh.y, vl.y);
            split_pair_f16(d.x, d.y, vh.z, vl.z);
            split_pair_f16(d.z, d.w, vh.w, vl.w);
            int off = (c ^ sw) << 4;
            *(uint4*)(bh + off) = vh;
            *(uint4*)(bl + off) = vl;
        }
        // reduce 4 lanes per row
        s  += __shfl_xor_sync(0xffffffffu, s, 1);
        ss += __shfl_xor_sync(0xffffffffu, ss, 1);
        s  += __shfl_xor_sync(0xffffffffu, s, 2);
        ss += __shfl_xor_sync(0xffffffffu, ss, 2);
        if (q == 0)
            g_part[(b * SLICES_ + slice) * N_ + j] = make_float2(s, ss);
    }
    __syncthreads();

    // ---- arrive + spin until all 16 slices of this batch posted partials ----
    if (tid == 0) {
        __threadfence();
        atomicAdd(&g_cnt[b], 1u);
        unsigned int v;
        do {
            asm volatile("ld.acquire.gpu.u32 %0, [%1];" : "=r"(v) : "l"(&g_cnt[b]) : "memory");
            if (v < (unsigned)SLICES_) __nanosleep(64);
        } while (v < (unsigned)SLICES_);
    }
    __syncthreads();

    // ---- energies for all 64 rows of batch b ----
    if (tid < N_) {
        float S = 0.f, SS = 0.f;
#pragma unroll
        for (int sl = 0; sl < SLICES_; sl++) {
            float2 p = g_part[(b * SLICES_ + sl) * N_ + tid];
            S += p.x; SS += p.y;
        }
        float mean = S * (1.f / T_);
        es[tid] = SS * (1.f / T_) - mean * mean;
    }
    __syncthreads();

    // ---- cooperative masked softmax: thread i (<64) computes row i ----
    if (tid < N_) {
        int i = tid;
        float cqk = 0.f, cqb = 0.f, cbk = 0.f, cbb = 0.f;
#pragma unroll
        for (int h = 0; h < H_; h++) {
            float wq = Wq[h], wk = Wk[h], vq = bq[h], vk = bk[h];
            cqk += wq * wk; cqb += wq * vk; cbk += vq * wk; cbb += vq * vk;
        }
        const float scale = 0.25f;
        float ei = es[i];
        float A = scale * (cqk * ei + cbk);
        float C = scale * (cqb * ei + cbb);
        float m = -3.4e38f;
#pragma unroll
        for (int j = 0; j < N_; j++) {
            float v = (j == i) ? -1e9f : (A * es[j] + C);
            m = fmaxf(m, v);
        }
        float sum = 0.f;
#pragma unroll
        for (int j = 0; j < N_; j++) {
            float v = (j == i) ? -1e9f : (A * es[j] + C);
            sum += expf(v - m);
        }
        float inv = 1.f / sum;
        float* sr = sAttn + i * SATT_STRIDE;
#pragma unroll
        for (int j = 0; j < N_; j++) {
            float v = (j == i) ? -1e9f : (A * es[j] + C);
            sr[j] = expf(v - m) * inv;
        }
        if (slice == 0) {
            float* outp = attnw + ((size_t)b * N_ + i) * N_;
#pragma unroll
            for (int j = 0; j < N_; j += 4)
                *(float4*)(outp + j) = make_float4(sr[j], sr[j + 1], sr[j + 2], sr[j + 3]);
        }
    }
    __syncthreads();

    // ---- persistent W fragments from smem attn tile ----
    uint32 Wf[4][4];
    {
        int r0 = it * 16 + g, r1 = r0 + 8;
#pragma unroll
        for (int ks = 0; ks < 4; ks++) {
            int col = ks * 16 + 2 * cq;
            float2 p0 = *(const float2*)(sAttn + r0 * SATT_STRIDE + col);
            float2 p1 = *(const float2*)(sAttn + r1 * SATT_STRIDE + col);
            float2 p2 = *(const float2*)(sAttn + r0 * SATT_STRIDE + col + 8);
            float2 p3 = *(const float2*)(sAttn + r1 * SATT_STRIDE + col + 8);
            Wf[ks][0] = pack_f16x2(p0.x, p0.y);
            Wf[ks][1] = pack_f16x2(p1.x, p1.y);
            Wf[ks][2] = pack_f16x2(p2.x, p2.y);
            Wf[ks][3] = pack_f16x2(p3.x, p3.y);
        }
    }

    uint32 baseXh = smem_u32(sXh);
    uint32 rb0 = (uint32)lane * 512;
    uint32 rb1 = (uint32)(lane + 32) * 512;
    uint32 rs = (uint32)(lane & 7);

    int i_r0 = it * 16 + g, i_r1 = i_r0 + 8;
    uint32 res_b0 = (uint32)i_r0 * 512 + (uint32)cq * 4;
    uint32 res_b1 = (uint32)i_r1 * 512 + (uint32)cq * 4;
    uint32 res_s0 = (uint32)(i_r0 & 7), res_s1 = (uint32)(i_r1 & 7);

#pragma unroll
    for (int chunk = 0; chunk < 16; chunk++) {
        uint32 tch = (uint32)(th * 16 + chunk);
        float acc[4] = {0.f, 0.f, 0.f, 0.f};
        uint32 sw = (tch ^ rs) << 4;
        {
            uint32 b0, b1, b2, b3;
            LDSM_X4_T(b0, b1, b2, b3, baseXh + rb0 + sw);      // rows 0..31
            MMA_F16(acc, Wf[0][0], Wf[0][1], Wf[0][2], Wf[0][3], b0, b1);
            MMA_F16(acc, Wf[1][0], Wf[1][1], Wf[1][2], Wf[1][3], b2, b3);
        }
        {
            uint32 b0, b1, b2, b3;
            LDSM_X4_T(b0, b1, b2, b3, baseXh + rb1 + sw);      // rows 32..63
            MMA_F16(acc, Wf[2][0], Wf[2][1], Wf[2][2], Wf[2][3], b0, b1);
            MMA_F16(acc, Wf[3][0], Wf[3][1], Wf[3][2], Wf[3][3], b2, b3);
        }

        // exact residual from smem (h + l) + store
        uint32 sw0 = (tch ^ res_s0) << 4;
        uint32 sw1 = (tch ^ res_s1) << 4;
        uint32 h0 = *(const uint32*)((char*)sXh + res_b0 + sw0);
        uint32 l0 = *(const uint32*)((char*)sXl + res_b0 + sw0);
        uint32 h1 = *(const uint32*)((char*)sXh + res_b1 + sw1);
        uint32 l1 = *(const uint32*)((char*)sXl + res_b1 + sw1);
        float2 xh0 = h2f2(h0), xl0 = h2f2(l0);
        float2 xh1 = h2f2(h1), xl1 = h2f2(l1);

        int tg = t_cta + (int)tch * 8 + 2 * cq;
        float2 o0 = make_float2(acc[0] + xh0.x + xl0.x, acc[1] + xh0.y + xl0.y);
        float2 o1 = make_float2(acc[2] + xh1.x + xl1.x, acc[3] + xh1.y + xl1.y);
        *(float2*)(ob + (size_t)i_r0 * T_ + tg) = o0;
        *(float2*)(ob + (size_t)i_r1 * T_ + tg) = o1;
    }
}

extern "C" void kernel_launch(void* const* d_in, const int* in_sizes, int n_in,
                              void* d_out, int out_size) {
    const float* x  = (const float*)d_in[0];
    const float* Wq = (const float*)d_in[1];
    const float* bq = (const float*)d_in[2];
    const float* Wk = (const float*)d_in[3];
    const float* bk = (const float*)d_in[4];

    float* out   = (float*)d_out;                 // [B,N,T,1]
    float* attnw = out + (size_t)B_ * N_ * T_;    // [B,N,N]

    const int smem_bytes = (2 * 64 * 128) * 4 + 64 * SATT_STRIDE * 4 + 64 * 4;
    cudaFuncSetAttribute(k_fused, cudaFuncAttributeMaxDynamicSharedMemorySize, smem_bytes);

    k_zero<<<1, B_>>>();
    k_fused<<<dim3(SLICES_, B_), 256, smem_bytes>>>(x, Wq, bq, Wk, bk, attnw, out);
}

// round 11
// speedup vs baseline: 1.0300x; 1.0300x over previous
#include <cuda_runtime.h>
#include <cuda_fp16.h>
#include <cstdint>

#define B_ 256
#define N_ 64
#define T_ 4096
#define H_ 16

typedef unsigned int uint32;

__device__ float g_energy[B_ * N_];

// ---------- helpers ----------
static __device__ __forceinline__ uint32 smem_u32(const void* p) {
    uint32 a;
    asm("{ .reg .u64 t; cvta.to.shared.u64 t, %1; cvt.u32.u64 %0, t; }" : "=r"(a) : "l"(p));
    return a;
}
static __device__ __forceinline__ uint32 pack_f16x2(float f0, float f1) {
    uint32 r;
    asm("cvt.rn.f16x2.f32 %0, %1, %2;" : "=r"(r) : "f"(f1), "f"(f0));
    return r;
}

#define MMA_F16(c, a0, a1, a2, a3, b0, b1) \
    asm volatile("mma.sync.aligned.m16n8k16.row.col.f32.f16.f16.f32 " \
        "{%0,%1,%2,%3}, {%4,%5,%6,%7}, {%8,%9}, {%0,%1,%2,%3};" \
        : "+f"((c)[0]), "+f"((c)[1]), "+f"((c)[2]), "+f"((c)[3]) \
        : "r"(a0), "r"(a1), "r"(a2), "r"(a3), "r"(b0), "r"(b1))

#define LDSM_X4_T(r0, r1, r2, r3, addr) \
    asm volatile("ldmatrix.sync.aligned.m8n8.x4.trans.shared.b16 {%0,%1,%2,%3}, [%4];" \
        : "=r"(r0), "=r"(r1), "=r"(r2), "=r"(r3) : "r"(addr))

// ---------- K1: variance (at HBM roofline) ----------
__global__ void __launch_bounds__(256) k_var(const float* __restrict__ x) {
    size_t base = (size_t)blockIdx.x * T_;
    const float4* xp = (const float4*)(x + base);
    float s = 0.f, ss = 0.f;
#pragma unroll
    for (int it = 0; it < 4; it++) {
        float4 v = xp[threadIdx.x + it * 256];
        s  += (v.x + v.y) + (v.z + v.w);
        ss += (v.x * v.x + v.y * v.y) + (v.z * v.z + v.w * v.w);
    }
#pragma unroll
    for (int o = 16; o; o >>= 1) {
        s  += __shfl_xor_sync(0xffffffffu, s, o);
        ss += __shfl_xor_sync(0xffffffffu, ss, o);
    }
    __shared__ float sh_s[8], sh_ss[8];
    if ((threadIdx.x & 31) == 0) { sh_s[threadIdx.x >> 5] = s; sh_ss[threadIdx.x >> 5] = ss; }
    __syncthreads();
    if (threadIdx.x == 0) {
        float S = 0.f, SS = 0.f;
#pragma unroll
        for (int w = 0; w < 8; w++) { S += sh_s[w]; SS += sh_ss[w]; }
        float mean = S * (1.f / T_);
        g_energy[blockIdx.x] = SS * (1.f / T_) - mean * mean;
    }
}

// ---------- K2: closed-form logits + masked softmax ----------
__global__ void __launch_bounds__(64) k_attn(const float* __restrict__ Wq,
                                             const float* __restrict__ bq,
                                             const float* __restrict__ Wk,
                                             const float* __restrict__ bk,
                                             float* __restrict__ attnw) {
    int b = blockIdx.x;
    int i = threadIdx.x;
    __shared__ float es[N_];
    es[i] = g_energy[b * N_ + i];

    float cqk = 0.f, cqb = 0.f, cbk = 0.f, cbb = 0.f;
#pragma unroll
    for (int h = 0; h < H_; h++) {
        float wq = Wq[h], wk = Wk[h], vq = bq[h], vk = bk[h];
        cqk += wq * wk; cqb += wq * vk; cbk += vq * wk; cbb += vq * vk;
    }
    __syncthreads();

    const float scale = 0.25f;
    float ei = es[i];
    float l[N_];
    float m = -3.4e38f;
#pragma unroll
    for (int j = 0; j < N_; j++) {
        float ej = es[j];
        float v = scale * (cqk * ei * ej + cqb * ei + cbk * ej + cbb);
        if (j == i) v = -1e9f;
        l[j] = v;
        m = fmaxf(m, v);
    }
    float sum = 0.f;
#pragma unroll
    for (int j = 0; j < N_; j++) { float e = expf(l[j] - m); l[j] = e; sum += e; }
    float inv = 1.f / sum;
    float* outp = attnw + ((size_t)b * N_ + i) * N_;
#pragma unroll
    for (int j = 0; j < N_; j += 4) {
        float4 v = make_float4(l[j] * inv, l[j + 1] * inv, l[j + 2] * inv, l[j + 3] * inv);
        *(float4*)(outp + j) = v;
    }
}

// ---------- K3: single-term fp16 mma.sync, 128-t tile, 16KB smem, residual from global ----------
// out[b,i,t] = x[b,i,t] + sum_j W[i,j] x[j,t]
// CTA: batch b, 128-t tile, 256 threads = 8 warps = (4 i-tiles of 16) x (2 t-halves of 64).
// Only the fp16-hi x tile lives in smem (MMA B operand via ldmatrix). The residual is
// re-read from global fp32 in the epilogue (L1/L2-hot: same lines staged moments before),
// keeping the dominant +x term exact. Small footprint -> 4+ CTAs/SM -> phase overlap.
__global__ void __launch_bounds__(256) k_out_mma(const float* __restrict__ x,
                                                 const float* __restrict__ attnw,
                                                 float* __restrict__ out) {
    __shared__ __align__(256) uint32 sXh[64 * 64];   // 64 rows x 128 fp16 = 16KB

    int b = blockIdx.y;
    int t_cta = blockIdx.x * 128;
    int tid = threadIdx.x;
    int lane = tid & 31;
    int wid = tid >> 5;
    int it = wid & 3;            // i-tile
    int th = wid >> 2;           // t-half (64 t each)
    int g = lane >> 2;           // fragment row group
    int cq = lane & 3;           // fragment col quad

    const float* xb = x + (size_t)b * (N_ * T_);
    float* ob = out + (size_t)b * (N_ * T_);

    // ---- stage x tile (64 j x 128 t) -> swizzled fp16-hi smem ----
    {
        int j = tid >> 2, q = tid & 3;
        const float* xrow = xb + (size_t)j * T_ + t_cta;
        char* bh = (char*)(sXh + j * 64);
        int sw = j & 7;
#pragma unroll
        for (int cc = 0; cc < 4; cc++) {
            int c = q + cc * 4;                 // chunk 0..15 (8 t each)
            float4 a = *(const float4*)(xrow + c * 8);
            float4 d = *(const float4*)(xrow + c * 8 + 4);
            uint4 vh;
            vh.x = pack_f16x2(a.x, a.y);
            vh.y = pack_f16x2(a.z, a.w);
            vh.z = pack_f16x2(d.x, d.y);
            vh.w = pack_f16x2(d.z, d.w);
            *(uint4*)(bh + ((c ^ sw) << 4)) = vh;
        }
    }

    // ---- persistent A (W) fragments: single fp16, 4 k-steps ----
    uint32 Wf[4][4];
    {
        const float* ar = attnw + (size_t)b * (N_ * N_);
        int r0 = it * 16 + g, r1 = r0 + 8;
#pragma unroll
        for (int ks = 0; ks < 4; ks++) {
            int col = ks * 16 + 2 * cq;
            float2 p0 = *(const float2*)(ar + r0 * 64 + col);
            float2 p1 = *(const float2*)(ar + r1 * 64 + col);
            float2 p2 = *(const float2*)(ar + r0 * 64 + col + 8);
            float2 p3 = *(const float2*)(ar + r1 * 64 + col + 8);
            Wf[ks][0] = pack_f16x2(p0.x, p0.y);
            Wf[ks][1] = pack_f16x2(p1.x, p1.y);
            Wf[ks][2] = pack_f16x2(p2.x, p2.y);
            Wf[ks][3] = pack_f16x2(p3.x, p3.y);
        }
    }
    __syncthreads();

    uint32 baseXh = smem_u32(sXh);
    uint32 rb0 = (uint32)lane * 256;            // rows j=0..31 (256B row stride)
    uint32 rb1 = (uint32)(lane + 32) * 256;     // rows j=32..63
    uint32 rs = (uint32)(lane & 7);

    int i_r0 = it * 16 + g, i_r1 = i_r0 + 8;
    const float* xr0 = xb + (size_t)i_r0 * T_ + t_cta;
    const float* xr1 = xb + (size_t)i_r1 * T_ + t_cta;
    float* or0 = ob + (size_t)i_r0 * T_ + t_cta;
    float* or1 = ob + (size_t)i_r1 * T_ + t_cta;

#pragma unroll
    for (int chunk = 0; chunk < 8; chunk++) {
        uint32 tch = (uint32)(th * 8 + chunk);
        float acc[4] = {0.f, 0.f, 0.f, 0.f};
        uint32 sw = (tch ^ rs) << 4;
        {
            uint32 b0, b1, b2, b3;
            LDSM_X4_T(b0, b1, b2, b3, baseXh + rb0 + sw);      // rows 0..31
            MMA_F16(acc, Wf[0][0], Wf[0][1], Wf[0][2], Wf[0][3], b0, b1);
            MMA_F16(acc, Wf[1][0], Wf[1][1], Wf[1][2], Wf[1][3], b2, b3);
        }
        {
            uint32 b0, b1, b2, b3;
            LDSM_X4_T(b0, b1, b2, b3, baseXh + rb1 + sw);      // rows 32..63
            MMA_F16(acc, Wf[2][0], Wf[2][1], Wf[2][2], Wf[2][3], b0, b1);
            MMA_F16(acc, Wf[3][0], Wf[3][1], Wf[3][2], Wf[3][3], b2, b3);
        }

        // exact fp32 residual from global (hot in L1/L2) + store
        int tg = (int)tch * 8 + 2 * cq;
        float2 x0 = *(const float2*)(xr0 + tg);
        float2 x1 = *(const float2*)(xr1 + tg);
        float2 o0 = make_float2(acc[0] + x0.x, acc[1] + x0.y);
        float2 o1 = make_float2(acc[2] + x1.x, acc[3] + x1.y);
        *(float2*)(or0 + tg) = o0;
        *(float2*)(or1 + tg) = o1;
    }
}

extern "C" void kernel_launch(void* const* d_in, const int* in_sizes, int n_in,
                              void* d_out, int out_size) {
    const float* x  = (const float*)d_in[0];
    const float* Wq = (const float*)d_in[1];
    const float* bq = (const float*)d_in[2];
    const float* Wk = (const float*)d_in[3];
    const float* bk = (const float*)d_in[4];

    float* out   = (float*)d_out;                 // [B,N,T,1]
    float* attnw = out + (size_t)B_ * N_ * T_;    // [B,N,N]

    k_var<<<B_ * N_, 256>>>(x);
    k_attn<<<B_, 64>>>(Wq, bq, Wk, bk, attnw);
    k_out_mma<<<dim3(T_ / 128, B_), 256>>>(x, attnw, out);
}

// round 13
// speedup vs baseline: 1.1914x; 1.1567x over previous
#include <cuda_runtime.h>
#include <cuda_fp16.h>
#include <cstdint>

#define B_ 256
#define N_ 64
#define T_ 4096
#define H_ 16

typedef unsigned int uint32;

__device__ float g_energy[B_ * N_];

// ---------- helpers ----------
static __device__ __forceinline__ uint32 smem_u32(const void* p) {
    uint32 a;
    asm("{ .reg .u64 t; cvta.to.shared.u64 t, %1; cvt.u32.u64 %0, t; }" : "=r"(a) : "l"(p));
    return a;
}
static __device__ __forceinline__ uint32 pack_f16x2(float f0, float f1) {
    uint32 r;
    asm("cvt.rn.f16x2.f32 %0, %1, %2;" : "=r"(r) : "f"(f1), "f"(f0));
    return r;
}
static __device__ __forceinline__ float2 h2f2(uint32 u) {
    __half2 h = *(__half2*)&u;
    return __half22float2(h);
}
static __device__ __forceinline__ void split_pair_f16(float f0, float f1, uint32& h, uint32& l) {
    h = pack_f16x2(f0, f1);
    float2 b = h2f2(h);
    l = pack_f16x2(f0 - b.x, f1 - b.y);
}

#define MMA_F16(c, a0, a1, a2, a3, b0, b1) \
    asm volatile("mma.sync.aligned.m16n8k16.row.col.f32.f16.f16.f32 " \
        "{%0,%1,%2,%3}, {%4,%5,%6,%7}, {%8,%9}, {%0,%1,%2,%3};" \
        : "+f"((c)[0]), "+f"((c)[1]), "+f"((c)[2]), "+f"((c)[3]) \
        : "r"(a0), "r"(a1), "r"(a2), "r"(a3), "r"(b0), "r"(b1))

#define LDSM_X4_T(r0, r1, r2, r3, addr) \
    asm volatile("ldmatrix.sync.aligned.m8n8.x4.trans.shared.b16 {%0,%1,%2,%3}, [%4];" \
        : "=r"(r0), "=r"(r1), "=r"(r2), "=r"(r3) : "r"(addr))

// ---------- K1: variance (at HBM roofline) ----------
__global__ void __launch_bounds__(256) k_var(const float* __restrict__ x) {
    size_t base = (size_t)blockIdx.x * T_;
    const float4* xp = (const float4*)(x + base);
    float s = 0.f, ss = 0.f;
#pragma unroll
    for (int it = 0; it < 4; it++) {
        float4 v = xp[threadIdx.x + it * 256];
        s  += (v.x + v.y) + (v.z + v.w);
        ss += (v.x * v.x + v.y * v.y) + (v.z * v.z + v.w * v.w);
    }
#pragma unroll
    for (int o = 16; o; o >>= 1) {
        s  += __shfl_xor_sync(0xffffffffu, s, o);
        ss += __shfl_xor_sync(0xffffffffu, ss, o);
    }
    __shared__ float sh_s[8], sh_ss[8];
    if ((threadIdx.x & 31) == 0) { sh_s[threadIdx.x >> 5] = s; sh_ss[threadIdx.x >> 5] = ss; }
    __syncthreads();
    if (threadIdx.x == 0) {
        float S = 0.f, SS = 0.f;
#pragma unroll
        for (int w = 0; w < 8; w++) { S += sh_s[w]; SS += sh_ss[w]; }
        float mean = S * (1.f / T_);
        g_energy[blockIdx.x] = SS * (1.f / T_) - mean * mean;
    }
}

// ---------- K2: closed-form logits + masked softmax ----------
__global__ void __launch_bounds__(64) k_attn(const float* __restrict__ Wq,
                                             const float* __restrict__ bq,
                                             const float* __restrict__ Wk,
                                             const float* __restrict__ bk,
                                             float* __restrict__ attnw) {
    int b = blockIdx.x;
    int i = threadIdx.x;
    __shared__ float es[N_];
    es[i] = g_energy[b * N_ + i];

    float cqk = 0.f, cqb = 0.f, cbk = 0.f, cbb = 0.f;
#pragma unroll
    for (int h = 0; h < H_; h++) {
        float wq = Wq[h], wk = Wk[h], vq = bq[h], vk = bk[h];
        cqk += wq * wk; cqb += wq * vk; cbk += vq * wk; cbb += vq * vk;
    }
    __syncthreads();

    const float scale = 0.25f;
    float ei = es[i];
    float l[N_];
    float m = -3.4e38f;
#pragma unroll
    for (int j = 0; j < N_; j++) {
        float ej = es[j];
        float v = scale * (cqk * ei * ej + cqb * ei + cbk * ej + cbb);
        if (j == i) v = -1e9f;
        l[j] = v;
        m = fmaxf(m, v);
    }
    float sum = 0.f;
#pragma unroll
    for (int j = 0; j < N_; j++) { float e = expf(l[j] - m); l[j] = e; sum += e; }
    float inv = 1.f / sum;
    float* outp = attnw + ((size_t)b * N_ + i) * N_;
#pragma unroll
    for (int j = 0; j < N_; j += 4) {
        float4 v = make_float4(l[j] * inv, l[j + 1] * inv, l[j + 2] * inv, l[j + 3] * inv);
        *(float4*)(outp + j) = v;
    }
}

// ---------- K3: single-term fp16 mma.sync, 256-t tile, occupancy 3 ----------
// out[b,i,t] = x[b,i,t] + sum_j W[i,j] x[j,t]
// CTA: batch b, 256-t tile, 256 threads = 8 warps = (4 i-tiles of 16) x (2 t-halves of 128).
// MMA uses only Xh (fp16-hi); Xl kept solely for exact residual (x = h + l to 2^-24).
// __launch_bounds__(256,3) caps regs at 85 so 3 CTAs (3x64KB=192KB smem) co-reside,
// overlapping the stage/compute/store phases across CTAs.
__global__ void __launch_bounds__(256, 3) k_out_mma(const float* __restrict__ x,
                                                    const float* __restrict__ attnw,
                                                    float* __restrict__ out) {
    extern __shared__ uint32 smem[];
    uint32* sXh = smem;                 // [64][128] u32 (f16x2) = 32KB, MMA + residual
    uint32* sXl = smem + 64 * 128;      // 32KB, residual only

    int b = blockIdx.y;
    int t_cta = blockIdx.x * 256;
    int tid = threadIdx.x;
    int lane = tid & 31;
    int wid = tid >> 5;
    int it = wid & 3;            // i-tile
    int th = wid >> 2;           // t-half (128 t each)
    int g = lane >> 2;           // fragment row group
    int cq = lane & 3;           // fragment col quad

    const float* xb = x + (size_t)b * (N_ * T_);
    float* ob = out + (size_t)b * (N_ * T_);

    // ---- stage x tile (64 j x 256 t) -> swizzled fp16 hi/lo smem ----
    {
        int j = tid >> 2, q = tid & 3;
        const float* xrow = xb + (size_t)j * T_ + t_cta;
        char* bh = (char*)(sXh + j * 128);
        char* bl = (char*)(sXl + j * 128);
        int sw = j & 7;
#pragma unroll
        for (int cc = 0; cc < 8; cc++) {
            int c = q + cc * 4;                 // chunk 0..31 (8 t each)
            float4 a = *(const float4*)(xrow + c * 8);
            float4 d = *(const float4*)(xrow + c * 8 + 4);
            uint4 vh, vl;
            split_pair_f16(a.x, a.y, vh.x, vl.x);
            split_pair_f16(a.z, a.w, vh.y, vl.y);
            split_pair_f16(d.x, d.y, vh.z, vl.z);
            split_pair_f16(d.z, d.w, vh.w, vl.w);
            int off = (c ^ sw) << 4;
            *(uint4*)(bh + off) = vh;
            *(uint4*)(bl + off) = vl;
        }
    }

    // ---- persistent A (W) fragments: single fp16, 4 k-steps ----
    uint32 Wf[4][4];
    {
        const float* ar = attnw + (size_t)b * (N_ * N_);
        int r0 = it * 16 + g, r1 = r0 + 8;
#pragma unroll
        for (int ks = 0; ks < 4; ks++) {
            int col = ks * 16 + 2 * cq;
            float2 p0 = *(const float2*)(ar + r0 * 64 + col);
            float2 p1 = *(const float2*)(ar + r1 * 64 + col);
            float2 p2 = *(const float2*)(ar + r0 * 64 + col + 8);
            float2 p3 = *(const float2*)(ar + r1 * 64 + col + 8);
            Wf[ks][0] = pack_f16x2(p0.x, p0.y);
            Wf[ks][1] = pack_f16x2(p1.x, p1.y);
            Wf[ks][2] = pack_f16x2(p2.x, p2.y);
            Wf[ks][3] = pack_f16x2(p3.x, p3.y);
        }
    }
    __syncthreads();

    uint32 baseXh = smem_u32(sXh);
    uint32 rb0 = (uint32)lane * 512;            // rows j=0..31
    uint32 rb1 = (uint32)(lane + 32) * 512;     // rows j=32..63
    uint32 rs = (uint32)(lane & 7);

    int i_r0 = it * 16 + g, i_r1 = i_r0 + 8;
    uint32 res_b0 = (uint32)i_r0 * 512 + (uint32)cq * 4;
    uint32 res_b1 = (uint32)i_r1 * 512 + (uint32)cq * 4;
    uint32 res_s0 = (uint32)(i_r0 & 7), res_s1 = (uint32)(i_r1 & 7);

#pragma unroll
    for (int chunk = 0; chunk < 16; chunk++) {
        uint32 tch = (uint32)(th * 16 + chunk);
        float acc[4] = {0.f, 0.f, 0.f, 0.f};
        uint32 sw = (tch ^ rs) << 4;
        {
            uint32 b0, b1, b2, b3;
            LDSM_X4_T(b0, b1, b2, b3, baseXh + rb0 + sw);      // rows 0..31
            MMA_F16(acc, Wf[0][0], Wf[0][1], Wf[0][2], Wf[0][3], b0, b1);
            MMA_F16(acc, Wf[1][0], Wf[1][1], Wf[1][2], Wf[1][3], b2, b3);
        }
        {
            uint32 b0, b1, b2, b3;
            LDSM_X4_T(b0, b1, b2, b3, baseXh + rb1 + sw);      // rows 32..63
            MMA_F16(acc, Wf[2][0], Wf[2][1], Wf[2][2], Wf[2][3], b0, b1);
            MMA_F16(acc, Wf[3][0], Wf[3][1], Wf[3][2], Wf[3][3], b2, b3);
        }

        // exact residual from smem (h + l) + store
        uint32 sw0 = (tch ^ res_s0) << 4;
        uint32 sw1 = (tch ^ res_s1) << 4;
        uint32 h0 = *(const uint32*)((char*)sXh + res_b0 + sw0);
        uint32 l0 = *(const uint32*)((char*)sXl + res_b0 + sw0);
        uint32 h1 = *(const uint32*)((char*)sXh + res_b1 + sw1);
        uint32 l1 = *(const uint32*)((char*)sXl + res_b1 + sw1);
        float2 xh0 = h2f2(h0), xl0 = h2f2(l0);
        float2 xh1 = h2f2(h1), xl1 = h2f2(l1);

        int tg = t_cta + (int)tch * 8 + 2 * cq;
        float2 o0 = make_float2(acc[0] + xh0.x + xl0.x, acc[1] + xh0.y + xl0.y);
        float2 o1 = make_float2(acc[2] + xh1.x + xl1.x, acc[3] + xh1.y + xl1.y);
        *(float2*)(ob + (size_t)i_r0 * T_ + tg) = o0;
        *(float2*)(ob + (size_t)i_r1 * T_ + tg) = o1;
    }
}

extern "C" void kernel_launch(void* const* d_in, const int* in_sizes, int n_in,
                              void* d_out, int out_size) {
    const float* x  = (const float*)d_in[0];
    const float* Wq = (const float*)d_in[1];
    const float* bq = (const float*)d_in[2];
    const float* Wk = (const float*)d_in[3];
    const float* bk = (const float*)d_in[4];

    float* out   = (float*)d_out;                 // [B,N,T,1]
    float* attnw = out + (size_t)B_ * N_ * T_;    // [B,N,N]

    cudaFuncSetAttribute(k_out_mma, cudaFuncAttributeMaxDynamicSharedMemorySize, 65536);

    k_var<<<B_ * N_, 256>>>(x);
    k_attn<<<B_, 64>>>(Wq, bq, Wk, bk, attnw);
    k_out_mma<<<dim3(T_ / 256, B_), 256, 65536>>>(x, attnw, out);
}

// round 14
// speedup vs baseline: 1.3219x; 1.1095x over previous
#include <cuda_runtime.h>
#include <cuda_fp16.h>
#include <cstdint>

#define B_ 256
#define N_ 64
#define T_ 4096
#define H_ 16
#define SLICES_ 16          // CTAs per batch, each owns 256 t

typedef unsigned int uint32;

__device__ float2 g_part[B_ * SLICES_ * N_];   // per (batch,slice,row): (sum, sumsq)
__device__ unsigned int g_cnt[B_];

// ---------- helpers ----------
static __device__ __forceinline__ uint32 smem_u32(const void* p) {
    uint32 a;
    asm("{ .reg .u64 t; cvta.to.shared.u64 t, %1; cvt.u32.u64 %0, t; }" : "=r"(a) : "l"(p));
    return a;
}
static __device__ __forceinline__ uint32 pack_f16x2(float f0, float f1) {
    uint32 r;
    asm("cvt.rn.f16x2.f32 %0, %1, %2;" : "=r"(r) : "f"(f1), "f"(f0));
    return r;
}
static __device__ __forceinline__ float2 h2f2(uint32 u) {
    __half2 h = *(__half2*)&u;
    return __half22float2(h);
}
static __device__ __forceinline__ void split_pair_f16(float f0, float f1, uint32& h, uint32& l) {
    h = pack_f16x2(f0, f1);
    float2 b = h2f2(h);
    l = pack_f16x2(f0 - b.x, f1 - b.y);
}

#define MMA_F16(c, a0, a1, a2, a3, b0, b1) \
    asm volatile("mma.sync.aligned.m16n8k16.row.col.f32.f16.f16.f32 " \
        "{%0,%1,%2,%3}, {%4,%5,%6,%7}, {%8,%9}, {%0,%1,%2,%3};" \
        : "+f"((c)[0]), "+f"((c)[1]), "+f"((c)[2]), "+f"((c)[3]) \
        : "r"(a0), "r"(a1), "r"(a2), "r"(a3), "r"(b0), "r"(b1))

#define LDSM_X4_T(r0, r1, r2, r3, addr) \
    asm volatile("ldmatrix.sync.aligned.m8n8.x4.trans.shared.b16 {%0,%1,%2,%3}, [%4];" \
        : "=r"(r0), "=r"(r1), "=r"(r2), "=r"(r3) : "r"(addr))

// ---------- K0: reset per-batch arrival counters (each graph replay) ----------
__global__ void k_zero() { g_cnt[threadIdx.x] = 0u; }

// ---------- fused kernel: variance + softmax + MMA + residual, x read from DRAM once ----------
// grid = (SLICES_, B_): CTA = (slice, batch). Slices of a batch are contiguous in
// dispatch order; resident wave (~444 CTAs at occ 3) >> 16 => spin-sync deadlock-free.
#define SATT_STRIDE 33      // u32 stride for f16x2 attn rows (padding kills bank conflicts)
__global__ void __launch_bounds__(256, 3) k_fused(const float* __restrict__ x,
                                                  const float* __restrict__ Wq,
                                                  const float* __restrict__ bq,
                                                  const float* __restrict__ Wk,
                                                  const float* __restrict__ bk,
                                                  float* __restrict__ attnw,
                                                  float* __restrict__ out) {
    extern __shared__ uint32 smem[];
    uint32* sXh = smem;                            // [64][128] f16x2 hi (32KB)
    uint32* sXl = smem + 64 * 128;                 // [64][128] f16x2 lo (32KB)
    uint32* sAtt = smem + 2 * 64 * 128;            // [64][SATT_STRIDE] f16x2 (8.4KB)
    float* es = (float*)(sAtt + 64 * SATT_STRIDE); // [64]

    int slice = blockIdx.x;
    int b = blockIdx.y;
    int t_cta = slice * 256;
    int tid = threadIdx.x;
    int lane = tid & 31;
    int wid = tid >> 5;
    int it = wid & 3;            // i-tile
    int th = wid >> 2;           // t-half (128 t each)
    int g = lane >> 2;           // fragment row group
    int cq = lane & 3;           // fragment col quad

    const float* xb = x + (size_t)b * (N_ * T_);
    float* ob = out + (size_t)b * (N_ * T_);

    // ---- pass 1: stage x slice -> swizzled fp16 hi/lo smem, accumulate sum/sumsq ----
    {
        int j = tid >> 2, q = tid & 3;
        const float* xrow = xb + (size_t)j * T_ + t_cta;
        char* bh = (char*)(sXh + j * 128);
        char* bl = (char*)(sXl + j * 128);
        int sw = j & 7;
        float s = 0.f, ss = 0.f;
#pragma unroll
        for (int cc = 0; cc < 8; cc++) {
            int c = q + cc * 4;
            float4 a = *(const float4*)(xrow + c * 8);
            float4 d = *(const float4*)(xrow + c * 8 + 4);
            s  += (a.x + a.y) + (a.z + a.w) + (d.x + d.y) + (d.z + d.w);
            ss += (a.x * a.x + a.y * a.y) + (a.z * a.z + a.w * a.w)
                + (d.x * d.x + d.y * d.y) + (d.z * d.z + d.w * d.w);
            uint4 vh, vl;
            split_pair_f16(a.x, a.y, vh.x, vl.x);
            split_pair_f16(a.z, a.w, vh.y, vl.y);
            split_pair_f16(d.x, d.y, vh.z, vl.z);
            split_pair_f16(d.z, d.w, vh.w, vl.w);
            int off = (c ^ sw) << 4;
            *(uint4*)(bh + off) = vh;
            *(uint4*)(bl + off) = vl;
        }
        s  += __shfl_xor_sync(0xffffffffu, s, 1);
        ss += __shfl_xor_sync(0xffffffffu, ss, 1);
        s  += __shfl_xor_sync(0xffffffffu, s, 2);
        ss += __shfl_xor_sync(0xffffffffu, ss, 2);
        if (q == 0)
            g_part[(b * SLICES_ + slice) * N_ + j] = make_float2(s, ss);
    }
    __syncthreads();

    // ---- arrive + spin until all slices of this batch posted partials ----
    if (tid == 0) {
        __threadfence();
        atomicAdd(&g_cnt[b], 1u);
        unsigned int v;
        do {
            asm volatile("ld.acquire.gpu.u32 %0, [%1];" : "=r"(v) : "l"(&g_cnt[b]) : "memory");
            if (v < (unsigned)SLICES_) __nanosleep(64);
        } while (v < (unsigned)SLICES_);
    }
    __syncthreads();

    // ---- energies for the 64 rows of batch b ----
    if (tid < N_) {
        float S = 0.f, SS = 0.f;
#pragma unroll
        for (int sl = 0; sl < SLICES_; sl++) {
            float2 p = g_part[(b * SLICES_ + sl) * N_ + tid];
            S += p.x; SS += p.y;
        }
        float mean = S * (1.f / T_);
        es[tid] = SS * (1.f / T_) - mean * mean;
    }
    __syncthreads();

    // ---- masked softmax: thread i (<64) computes row i; pack f16x2 into smem ----
    if (tid < N_) {
        int i = tid;
        float cqk = 0.f, cqb = 0.f, cbk = 0.f, cbb = 0.f;
#pragma unroll
        for (int h = 0; h < H_; h++) {
            float wq = Wq[h], wk = Wk[h], vq = bq[h], vk = bk[h];
            cqk += wq * wk; cqb += wq * vk; cbk += vq * wk; cbb += vq * vk;
        }
        const float scale = 0.25f;
        float ei = es[i];
        float A = scale * (cqk * ei + cbk);
        float C = scale * (cqb * ei + cbb);
        float l[N_];
        float m = -3.4e38f;
#pragma unroll
        for (int j = 0; j < N_; j++) {
            float v = (j == i) ? -1e9f : (A * es[j] + C);
            l[j] = v;
            m = fmaxf(m, v);
        }
        float sum = 0.f;
#pragma unroll
        for (int j = 0; j < N_; j++) { float e = expf(l[j] - m); l[j] = e; sum += e; }
        float inv = 1.f / sum;
#pragma unroll
        for (int j = 0; j < N_; j++) l[j] *= inv;

        uint32* sr = sAtt + i * SATT_STRIDE;
#pragma unroll
        for (int jj = 0; jj < 32; jj++)
            sr[jj] = pack_f16x2(l[2 * jj], l[2 * jj + 1]);

        if (slice == 0) {
            float* outp = attnw + ((size_t)b * N_ + i) * N_;
#pragma unroll
            for (int j = 0; j < N_; j += 4)
                *(float4*)(outp + j) = make_float4(l[j], l[j + 1], l[j + 2], l[j + 3]);
        }
    }
    __syncthreads();

    // ---- persistent W fragments from f16x2 smem attn tile ----
    uint32 Wf[4][4];
    {
        int r0 = it * 16 + g, r1 = r0 + 8;
#pragma unroll
        for (int ks = 0; ks < 4; ks++) {
            Wf[ks][0] = sAtt[r0 * SATT_STRIDE + ks * 8 + cq];
            Wf[ks][1] = sAtt[r1 * SATT_STRIDE + ks * 8 + cq];
            Wf[ks][2] = sAtt[r0 * SATT_STRIDE + ks * 8 + cq + 4];
            Wf[ks][3] = sAtt[r1 * SATT_STRIDE + ks * 8 + cq + 4];
        }
    }

    uint32 baseXh = smem_u32(sXh);
    uint32 rb0 = (uint32)lane * 512;            // rows j=0..31
    uint32 rb1 = (uint32)(lane + 32) * 512;     // rows j=32..63
    uint32 rs = (uint32)(lane & 7);

    int i_r0 = it * 16 + g, i_r1 = i_r0 + 8;
    uint32 res_b0 = (uint32)i_r0 * 512 + (uint32)cq * 4;
    uint32 res_b1 = (uint32)i_r1 * 512 + (uint32)cq * 4;
    uint32 res_s0 = (uint32)(i_r0 & 7), res_s1 = (uint32)(i_r1 & 7);

#pragma unroll
    for (int chunk = 0; chunk < 16; chunk++) {
        uint32 tch = (uint32)(th * 16 + chunk);
        float acc[4] = {0.f, 0.f, 0.f, 0.f};
        uint32 sw = (tch ^ rs) << 4;
        {
            uint32 b0, b1, b2, b3;
            LDSM_X4_T(b0, b1, b2, b3, baseXh + rb0 + sw);      // rows 0..31
            MMA_F16(acc, Wf[0][0], Wf[0][1], Wf[0][2], Wf[0][3], b0, b1);
            MMA_F16(acc, Wf[1][0], Wf[1][1], Wf[1][2], Wf[1][3], b2, b3);
        }
        {
            uint32 b0, b1, b2, b3;
            LDSM_X4_T(b0, b1, b2, b3, baseXh + rb1 + sw);      // rows 32..63
            MMA_F16(acc, Wf[2][0], Wf[2][1], Wf[2][2], Wf[2][3], b0, b1);
            MMA_F16(acc, Wf[3][0], Wf[3][1], Wf[3][2], Wf[3][3], b2, b3);
        }

        // exact residual from smem (h + l) + store
        uint32 sw0 = (tch ^ res_s0) << 4;
        uint32 sw1 = (tch ^ res_s1) << 4;
        uint32 h0 = *(const uint32*)((char*)sXh + res_b0 + sw0);
        uint32 l0 = *(const uint32*)((char*)sXl + res_b0 + sw0);
        uint32 h1 = *(const uint32*)((char*)sXh + res_b1 + sw1);
        uint32 l1 = *(const uint32*)((char*)sXl + res_b1 + sw1);
        float2 xh0 = h2f2(h0), xl0 = h2f2(l0);
        float2 xh1 = h2f2(h1), xl1 = h2f2(l1);

        int tg = t_cta + (int)tch * 8 + 2 * cq;
        float2 o0 = make_float2(acc[0] + xh0.x + xl0.x, acc[1] + xh0.y + xl0.y);
        float2 o1 = make_float2(acc[2] + xh1.x + xl1.x, acc[3] + xh1.y + xl1.y);
        *(float2*)(ob + (size_t)i_r0 * T_ + tg) = o0;
        *(float2*)(ob + (size_t)i_r1 * T_ + tg) = o1;
    }
}

extern "C" void kernel_launch(void* const* d_in, const int* in_sizes, int n_in,
                              void* d_out, int out_size) {
    const float* x  = (const float*)d_in[0];
    const float* Wq = (const float*)d_in[1];
    const float* bq = (const float*)d_in[2];
    const float* Wk = (const float*)d_in[3];
    const float* bk = (const float*)d_in[4];

    float* out   = (float*)d_out;                 // [B,N,T,1]
    float* attnw = out + (size_t)B_ * N_ * T_;    // [B,N,N]

    const int smem_bytes = 2 * 64 * 128 * 4 + 64 * SATT_STRIDE * 4 + 64 * 4;  // 74240
    cudaFuncSetAttribute(k_fused, cudaFuncAttributeMaxDynamicSharedMemorySize, smem_bytes);

    k_zero<<<1, B_>>>();
    k_fused<<<dim3(SLICES_, B_), 256, smem_bytes>>>(x, Wq, bq, Wk, bk, attnw, out);
}